// round 1
// baseline (speedup 1.0000x reference)
#include <cuda_runtime.h>

// Problem: y = conv2d(x[1,512,512,16], w[3,3,16,64], SAME, stride 1)
//          pot = y + old_pot; spike = pot >= 1.0; new_pot = spike ? 0 : pot
// Outputs concatenated in d_out: [spikes (512*512*64)] [new_pot (512*512*64)]

#define HH 512
#define WW 512
#define CIN 16
#define COUT 64
#define TH 16
#define TW 16

#define WELEMS (9 * 16 * 64)          /* 9216 floats of weights */
#define INPITCHX 20                   /* padded x-pitch (floats) for bank-conflict-free LDS */
#define INPITCHY ((TW + 2) * INPITCHX) /* 18*20 = 360 */
#define INELEMS ((TH + 2) * INPITCHY)  /* 18*360 = 6480 */
#define SMEM_BYTES ((WELEMS + INELEMS) * 4) /* 62784 bytes */

__device__ __forceinline__ unsigned long long pack2(float x) {
    unsigned long long v;
    asm("mov.b64 %0, {%1, %1};" : "=l"(v) : "f"(x));
    return v;
}
__device__ __forceinline__ void ffma2(unsigned long long& d,
                                      unsigned long long a,
                                      unsigned long long b) {
    asm("fma.rn.f32x2 %0, %1, %2, %0;" : "+l"(d) : "l"(a), "l"(b));
}
__device__ __forceinline__ float2 unpack2(unsigned long long v) {
    float2 r;
    asm("mov.b64 {%0, %1}, %2;" : "=f"(r.x), "=f"(r.y) : "l"(v));
    return r;
}

__global__ void __launch_bounds__(256, 2)
snn_conv_kernel(const float* __restrict__ in, const float* __restrict__ wt,
                const float* __restrict__ oldp,
                float* __restrict__ out_spk, float* __restrict__ out_pot) {
    extern __shared__ float smem[];
    float* s_w = smem;               // [9][16][64]
    float* s_in = smem + WELEMS;     // [18][18(pitch 20)][16]

    const int tid = threadIdx.x;
    const int x0 = blockIdx.x * TW;
    const int y0 = blockIdx.y * TH;

    // ---- stage weights (broadcast via L2) ----
    {
        const float4* src = (const float4*)wt;
        float4* dst = (float4*)s_w;
        #pragma unroll
        for (int i = tid; i < WELEMS / 4; i += 256) dst[i] = src[i];
    }
    // ---- stage input tile with zero-padded halo ----
    for (int i = tid; i < 18 * 18 * 4; i += 256) {
        int v = i & 3;          // which float4 of the 16 input channels
        int xy = i >> 2;
        int sy = xy / 18;
        int sx = xy - sy * 18;
        int gy = y0 + sy - 1;
        int gx = x0 + sx - 1;
        float4 val = make_float4(0.f, 0.f, 0.f, 0.f);
        if ((unsigned)gy < HH && (unsigned)gx < WW)
            val = *(const float4*)(in + (gy * WW + gx) * CIN + v * 4);
        *(float4*)(s_in + sy * INPITCHY + sx * INPITCHX + v * 4) = val;
    }
    __syncthreads();

    // thread -> 8 output channels (cg*8..+7) x 8 y-adjacent pixels (fixed x)
    const int cg = tid & 7;
    const int pg = tid >> 3;
    const int px = pg & 15;
    const int py0 = (pg >> 4) * 8;

    unsigned long long acc[8][4];  // [pixel][channel-pair] packed f32x2
    #pragma unroll
    for (int p = 0; p < 8; p++)
        #pragma unroll
        for (int j = 0; j < 4; j++) acc[p][j] = 0ull;

    const float* wcg = s_w + cg * 8;
    #pragma unroll 1
    for (int k = 0; k < 9; k++) {   // dy*3+dx; keep body = 1 tap to fit I$
        const int dy = k / 3;
        const int dx = k - dy * 3;
        const float* wbase = wcg + k * (16 * 64);
        const float* ibase = s_in + (py0 + dy) * INPITCHY + (px + dx) * INPITCHX;
        #pragma unroll
        for (int ci = 0; ci < 16; ci++) {
            // 8 contiguous weights for this (tap, ci) as 4 packed f32x2 pairs
            ulonglong2 w01 = *(const ulonglong2*)(wbase + ci * 64);
            ulonglong2 w23 = *(const ulonglong2*)(wbase + ci * 64 + 4);
            #pragma unroll
            for (int p = 0; p < 8; p++) {
                unsigned long long xv = pack2(ibase[p * INPITCHY + ci]);
                ffma2(acc[p][0], xv, w01.x);
                ffma2(acc[p][1], xv, w01.y);
                ffma2(acc[p][2], xv, w23.x);
                ffma2(acc[p][3], xv, w23.y);
            }
        }
    }

    // ---- epilogue: add old potential, threshold, reset, store both outputs ----
    const int gx = x0 + px;
    #pragma unroll
    for (int p = 0; p < 8; p++) {
        int gy = y0 + py0 + p;
        int base = (gy * WW + gx) * COUT + cg * 8;
        float4 o0 = *(const float4*)(oldp + base);
        float4 o1 = *(const float4*)(oldp + base + 4);
        float2 a0 = unpack2(acc[p][0]);
        float2 a1 = unpack2(acc[p][1]);
        float2 a2 = unpack2(acc[p][2]);
        float2 a3 = unpack2(acc[p][3]);
        float v[8] = {a0.x + o0.x, a0.y + o0.y, a1.x + o0.z, a1.y + o0.w,
                      a2.x + o1.x, a2.y + o1.y, a3.x + o1.z, a3.y + o1.w};
        float s[8], q[8];
        #pragma unroll
        for (int j = 0; j < 8; j++) {
            bool fired = v[j] >= 1.0f;
            s[j] = fired ? 1.0f : 0.0f;
            q[j] = fired ? 0.0f : v[j];
        }
        *(float4*)(out_spk + base)     = make_float4(s[0], s[1], s[2], s[3]);
        *(float4*)(out_spk + base + 4) = make_float4(s[4], s[5], s[6], s[7]);
        *(float4*)(out_pot + base)     = make_float4(q[0], q[1], q[2], q[3]);
        *(float4*)(out_pot + base + 4) = make_float4(q[4], q[5], q[6], q[7]);
    }
}

extern "C" void kernel_launch(void* const* d_in, const int* in_sizes, int n_in,
                              void* d_out, int out_size) {
    const float* in   = (const float*)d_in[0];   // [1,512,512,16]
    const float* wt   = (const float*)d_in[1];   // [3,3,16,64]
    const float* oldp = (const float*)d_in[2];   // [1,512,512,64]
    float* spk = (float*)d_out;
    float* pot = (float*)d_out + in_sizes[2];    // second tuple element

    cudaFuncSetAttribute(snn_conv_kernel,
                         cudaFuncAttributeMaxDynamicSharedMemorySize, SMEM_BYTES);

    dim3 grid(WW / TW, HH / TH);  // 32 x 32 blocks
    snn_conv_kernel<<<grid, 256, SMEM_BYTES>>>(in, wt, oldp, spk, pot);
}